// round 7
// baseline (speedup 1.0000x reference)
#include <cuda_runtime.h>
#include <cstdint>

#define GMAX   64
#define BGROUP 4
#define NTHR   128

__global__ void __launch_bounds__(NTHR, 14)
ssd_target_kernel(const float* __restrict__ gt,
                  const int*   __restrict__ cls,
                  const float* __restrict__ anchors,
                  float*       __restrict__ out,
                  int B, int A)
{
    __shared__ float4 s_box [BGROUP * GMAX];   // y1,x1,y2,x2
    __shared__ float  s_area[BGROUP * GMAX];
    __shared__ float  s_cls [BGROUP * GMAX];
    __shared__ int    s_cnt [BGROUP];          // padded count (multiple of 4)

    const int wid  = threadIdx.x >> 5;
    const int lane = threadIdx.x & 31;
    const int nw   = blockDim.x >> 5;

    const int b0 = blockIdx.y * BGROUP;
    const int nb = min(BGROUP, B - b0);

    // ---- per-batch order-preserving compaction of valid GTs (warp ballot) ----
    for (int lb = wid; lb < nb; lb += nw) {
        const int gbase = (b0 + lb) * GMAX;
        const int sbase = lb * GMAX;
        int cnt = 0;
        #pragma unroll
        for (int chunk = 0; chunk < GMAX / 32; ++chunk) {
            const int g = chunk * 32 + lane;
            const float* gp = gt + (size_t)(gbase + g) * 5;
            float y1 = gp[0], x1 = gp[1], y2 = gp[2], x2 = gp[3], tg = gp[4];
            bool valid = (tg != 0.0f);
            unsigned m = __ballot_sync(0xffffffffu, valid);
            int pos = cnt + __popc(m & ((1u << lane) - 1u));
            if (valid) {
                s_box [sbase + pos] = make_float4(y1, x1, y2, x2);
                s_area[sbase + pos] = __fmul_rn(__fsub_rn(x2, x1), __fsub_rn(y2, y1));
                s_cls [sbase + pos] = (float)cls[(size_t)(gbase + g) * 2];
            }
            cnt += __popc(m);
        }
        if (lane == 0 && cnt == 0) {
            // reference: argmax over all -1 == index 0; deltas from raw gt[0]
            const float* gp = gt + (size_t)gbase * 5;
            float y1 = gp[0], x1 = gp[1], y2 = gp[2], x2 = gp[3];
            s_box [sbase] = make_float4(y1, x1, y2, x2);
            s_area[sbase] = __fmul_rn(__fsub_rn(x2, x1), __fsub_rn(y2, y1));
            s_cls [sbase] = (float)cls[(size_t)gbase * 2];
        }
        // pad to multiple of 4 with never-win dummies (inter==0, area==0)
        const int cnt_eff = (cnt == 0) ? 1 : cnt;
        const int cnt_pad = (cnt_eff + 3) & ~3;
        if (lane < cnt_pad - cnt_eff) {
            const int p = sbase + cnt_eff + lane;
            s_box [p] = make_float4(0.0f, 0.0f, 0.0f, 0.0f);
            s_area[p] = 0.0f;
            s_cls [p] = 0.0f;
        }
        if (lane == 0) s_cnt[lb] = cnt_pad;
    }
    __syncthreads();

    const int a = blockIdx.x * NTHR + threadIdx.x;
    if (a >= A) return;

    // Minimal loop-live anchor state (keeps regs low -> 14 blocks/SM)
    const float4 an = __ldg(reinterpret_cast<const float4*>(anchors) + a);
    const float area_an = __fmul_rn(__fsub_rn(an.w, an.y), __fsub_rn(an.z, an.x));

    const size_t N = (size_t)B * (size_t)A;
    float4* out4 = reinterpret_cast<float4*>(out); // deltas  [0, 4N)
    float*  outc = out + 4 * N;                    // classes [4N, 5N)
    float*  outt = out + 5 * N;                    // tags    [5N, 6N)
    const float KLOG = 3.4657359027997265f;        // ln(2)/0.2 (folds /0.2 BBOX_STD)

    for (int lb = 0; lb < nb; ++lb) {
        const int sbase = lb * GMAX;
        const int cntp  = s_cnt[lb];
        const float4* bp = s_box  + sbase;
        const float*  ap = s_area + sbase;

        // Division/union-free argmax:
        //   iou_j > iou_b  <=>  inter_j * S_b > inter_b * S_j,  S = area_gt + area_an
        // max(0,x)==__saturatef(x) (all extents < 1). Dummies (inter=0,area=0)
        // never beat a real/filled entry; real entry 0 always beats the sentinel.
        float bi = -1.0f, bS = 0.0f; int bj = 0;   // sentinel: iou = -1/(0-(-1)) = -1

        #define IOU_TERMS(g, ag, iv, Sv)                                           \
            {                                                                      \
                float iw = __saturatef(__fsub_rn(fminf((g).w, an.w),               \
                                                 fmaxf((g).y, an.y)));             \
                float ih = __saturatef(__fsub_rn(fminf((g).z, an.z),               \
                                                 fmaxf((g).x, an.x)));             \
                iv = __fmul_rn(iw, ih);                                            \
                Sv = __fadd_rn((ag), area_an);                                     \
            }
        #define UPD(iv, Sv, jj)                                                    \
            {                                                                      \
                bool better = __fmul_rn((iv), bS) > __fmul_rn(bi, (Sv));           \
                bi = better ? (iv) : bi;                                           \
                bS = better ? (Sv) : bS;                                           \
                bj = better ? (jj) : bj;                                           \
            }

        for (int j = 0; j < cntp; j += 4) {
            const float4 g0 = bp[j + 0]; const float a0 = ap[j + 0];
            const float4 g1 = bp[j + 1]; const float a1 = ap[j + 1];
            const float4 g2 = bp[j + 2]; const float a2 = ap[j + 2];
            const float4 g3 = bp[j + 3]; const float a3 = ap[j + 3];
            float i0, S0, i1, S1, i2, S2, i3, S3;
            IOU_TERMS(g0, a0, i0, S0)
            IOU_TERMS(g1, a1, i1, S1)
            IOU_TERMS(g2, a2, i2, S2)
            IOU_TERMS(g3, a3, i3, S3)
            UPD(i0, S0, j + 0)
            UPD(i1, S1, j + 1)
            UPD(i2, S2, j + 2)
            UPD(i3, S3, j + 3)
        }
        #undef IOU_TERMS
        #undef UPD

        // winner union with reference rounding: u = (area_gt + area_an) - inter
        const float iou_max = __fdiv_rn(bi, __fsub_rn(bS, bi));
        const float tagv = (iou_max >= 0.5f) ? 1.0f
                          : ((iou_max < 0.4f) ? -1.0f : 0.0f);

        // Epilogue: recompute winner meta + anchor constants here (not loop-live)
        const float4 g = bp[bj];
        const float ah = an.z - an.x, aw = an.w - an.y;
        const float acy = (an.z + an.x) * 0.5f, acx = (an.w + an.y) * 0.5f;
        const float gcy = (g.z + g.x) * 0.5f,   gcx = (g.w + g.y) * 0.5f;
        const float dy = (gcy - acy) * (10.0f / ah);
        const float dx = (gcx - acx) * (10.0f / aw);
        const float dh = (log2f(g.z - g.x) - log2f(ah)) * KLOG;
        const float dw = (log2f(g.w - g.y) - log2f(aw)) * KLOG;

        const size_t idx = (size_t)(b0 + lb) * (size_t)A + (size_t)a;
        out4[idx] = make_float4(dy, dx, dh, dw);
        outc[idx] = s_cls[sbase + bj];
        outt[idx] = tagv;
    }
}

extern "C" void kernel_launch(void* const* d_in, const int* in_sizes, int n_in,
                              void* d_out, int out_size)
{
    const float* gt      = (const float*)d_in[0];   // [B, 64, 5]
    const int*   cls     = (const int*)  d_in[1];   // [B, 64, 2]
    const float* anchors = (const float*)d_in[2];   // [A, 4]
    float* out = (float*)d_out;

    const int A = in_sizes[2] / 4;
    const int B = in_sizes[0] / (GMAX * 5);

    dim3 grid((A + NTHR - 1) / NTHR, (B + BGROUP - 1) / BGROUP);
    ssd_target_kernel<<<grid, NTHR>>>(gt, cls, anchors, out, B, A);
}